// round 2
// baseline (speedup 1.0000x reference)
#include <cuda_runtime.h>
#include <math.h>

#define TT   512      // Ttot = T*Ts
#define BB   128      // batch
#define HH   512      // hidden
#define CC   32       // input channels
#define TIN  128      // input time steps
#define NCHN 2048     // H*Ts conv output channels
#define HORZ 96
#define NELEM (TT*BB*HH)   // 33,554,432

// ---------------- scratch (device globals; no allocs allowed) ----------------
__device__ float g_conv[BB*NCHN*TIN];   // (B, 2048, T)
__device__ float g_bufA[NELEM];         // (Ttot, B, H)
__device__ float g_bufB[NELEM];
__device__ float g_Q[NELEM];
__device__ float g_K[NELEM];
__device__ float g_V[NELEM];
__device__ float g_wpart[4*BB*TT];
__device__ float g_wsum[BB*TT];
__device__ float g_feat[BB*HH];
__device__ float g_featn[BB*HH];
__device__ float g_chm[NCHN];
__device__ float g_chr[NCHN];

// ---------------- conv1d (C->NCHN, k=3, pad=1), 8 channels per block --------
__global__ void conv_kernel(const float* __restrict__ x,
                            const float* __restrict__ w,
                            const float* __restrict__ cb) {
    __shared__ float xs[130][33];     // time rows -1..128, padded cols
    __shared__ float ws[8*96];
    int b  = blockIdx.y;
    int c0 = blockIdx.x * 8;
    int t  = threadIdx.x;             // 128 threads = output time
    for (int i = t; i < 130*32; i += 128) {
        int r = i >> 5, ci = i & 31;
        int tt = r - 1;
        xs[r][ci] = (tt >= 0 && tt < TIN) ? x[(b*TIN + tt)*CC + ci] : 0.0f;
    }
    for (int i = t; i < 8*96; i += 128) ws[i] = w[c0*96 + i];
    __syncthreads();

    float acc[8];
    #pragma unroll
    for (int cc = 0; cc < 8; cc++) acc[cc] = cb[c0+cc];
    #pragma unroll
    for (int i = 0; i < 32; i++) {
        float x0 = xs[t][i], x1 = xs[t+1][i], x2 = xs[t+2][i];
        #pragma unroll
        for (int cc = 0; cc < 8; cc++) {
            acc[cc] += ws[cc*96 + i*3+0]*x0
                     + ws[cc*96 + i*3+1]*x1
                     + ws[cc*96 + i*3+2]*x2;
        }
    }
    #pragma unroll
    for (int cc = 0; cc < 8; cc++)
        g_conv[(b*NCHN + c0+cc)*TIN + t] = acc[cc];
}

// ---------------- per-channel BN1 stats over (B,T) ---------------------------
__global__ void chan_stats_kernel() {
    int c = blockIdx.x;
    int tid = threadIdx.x;  // 256
    float s = 0.f, sq = 0.f;
    for (int i = tid; i < BB*TIN; i += 256) {
        int b = i >> 7, t = i & 127;
        float v = g_conv[(b*NCHN + c)*TIN + t];
        s += v; sq += v*v;
    }
    __shared__ float ss[256], sqs[256];
    ss[tid] = s; sqs[tid] = sq;
    __syncthreads();
    for (int o = 128; o > 0; o >>= 1) {
        if (tid < o) { ss[tid] += ss[tid+o]; sqs[tid] += sqs[tid+o]; }
        __syncthreads();
    }
    if (tid == 0) {
        float m   = ss[0] * (1.0f/(BB*TIN));
        float var = sqs[0] * (1.0f/(BB*TIN)) - m*m;
        g_chm[c] = m;
        g_chr[c] = rsqrtf(var + 1e-5f);
    }
}

// ---------------- BN1 apply + relayout (B,2048,T) -> (Ttot,B,H) -------------
__global__ void bn1_apply_kernel(const float* __restrict__ g,
                                 const float* __restrict__ bb) {
    int idx = blockIdx.x*256 + threadIdx.x;   // output index in (tau,b,hh)
    int hh  = idx & 511;
    int b   = (idx >> 9) & 127;
    int tau = idx >> 16;
    int t   = tau >> 2, ts = tau & 3;
    int c   = ts*HH + hh;
    float v = g_conv[(b*NCHN + c)*TIN + t];
    g_bufA[idx] = (v - g_chm[c]) * g_chr[c] * g[c] + bb[c];
}

// ---------------- LIF scan: g_bufA -> g_bufB ---------------------------------
__global__ void lif_scan_kernel(const float* __restrict__ beta_arr, int store_mem) {
    int idx = blockIdx.x*blockDim.x + threadIdx.x;  // 0..65535  (b*H + h)
    float beta = fminf(fmaxf(beta_arr[idx & 511], 0.0f), 0.99f);
    float mem = 0.0f;
    #pragma unroll 4
    for (int t = 0; t < TT; t++) {
        float cur   = g_bufA[t*(BB*HH) + idx];
        float reset = (mem > 1.0f) ? 1.0f : 0.0f;
        mem = beta*mem + cur - reset;
        float sp = (mem > 1.0f) ? 1.0f : 0.0f;
        g_bufB[t*(BB*HH) + idx] = store_mem ? mem : sp;
    }
}

// ---------------- per-step BN over batch: g_bufB -> g_bufA -------------------
__global__ void bn_step_kernel(const float* __restrict__ g,
                               const float* __restrict__ bb) {
    int t = blockIdx.x;
    int h = blockIdx.y*128 + threadIdx.x;
    int base = t*(BB*HH) + h;
    float s = 0.f, sq = 0.f;
    #pragma unroll 4
    for (int b = 0; b < BB; b++) {
        float v = g_bufB[base + b*HH];
        s += v; sq += v*v;
    }
    float m    = s * (1.0f/BB);
    float rstd = rsqrtf(sq*(1.0f/BB) - m*m + 1e-5f);
    float gg = g[h]*rstd;
    float bo = bb[h] - m*gg;
    #pragma unroll 4
    for (int b = 0; b < BB; b++)
        g_bufA[base + b*HH] = g_bufB[base + b*HH]*gg + bo;
}

// ---------------- GEMM: C(sel) = mem3(65536x512) @ W^T + bias ---------------
__global__ __launch_bounds__(256) void gemm_xwT_kernel(int sel,
        const float* __restrict__ W, const float* __restrict__ bias) {
    const float* __restrict__ A = g_bufB;  // mem3, row m = t*B + b
    float* __restrict__ C = (sel == 0) ? g_Q : (sel == 1) ? g_K : g_V;

    __shared__ __align__(16) float As[16][128];
    __shared__ __align__(16) float Bs[16][128];
    int tid = threadIdx.x;
    int n0 = blockIdx.x * 128;
    int m0 = blockIdx.y * 128;
    int tx = tid & 15, ty = tid >> 4;
    float acc[8][8] = {};

    for (int k0 = 0; k0 < HH; k0 += 16) {
        #pragma unroll
        for (int it = 0; it < 2; it++) {
            int flat = tid + it*256;
            int r = flat >> 2, c = flat & 3;
            float4 va = *(const float4*)(A + (m0 + r)*HH + k0 + c*4);
            As[c*4+0][r] = va.x; As[c*4+1][r] = va.y;
            As[c*4+2][r] = va.z; As[c*4+3][r] = va.w;
            float4 vb = *(const float4*)(W + (n0 + r)*HH + k0 + c*4);
            Bs[c*4+0][r] = vb.x; Bs[c*4+1][r] = vb.y;
            Bs[c*4+2][r] = vb.z; Bs[c*4+3][r] = vb.w;
        }
        __syncthreads();
        #pragma unroll
        for (int k = 0; k < 16; k++) {
            float a[8], b[8];
            *(float4*)(a)   = *(const float4*)&As[k][ty*8];
            *(float4*)(a+4) = *(const float4*)&As[k][ty*8+4];
            *(float4*)(b)   = *(const float4*)&Bs[k][tx*8];
            *(float4*)(b+4) = *(const float4*)&Bs[k][tx*8+4];
            #pragma unroll
            for (int i = 0; i < 8; i++)
                #pragma unroll
                for (int j = 0; j < 8; j++)
                    acc[i][j] += a[i]*b[j];
        }
        __syncthreads();
    }
    #pragma unroll
    for (int i = 0; i < 8; i++) {
        int m = m0 + ty*8 + i;
        #pragma unroll
        for (int j = 0; j < 8; j++)
            C[m*HH + n0 + tx*8 + j] = acc[i][j] + bias[n0 + tx*8 + j];
    }
}

// ---------------- per-batch QK^T + sigmoid + column mean partials -----------
__global__ __launch_bounds__(256) void qk_attn_kernel() {
    __shared__ __align__(16) float As[16][128];
    __shared__ __align__(16) float Bs[16][128];
    __shared__ float red[16][128];
    int b  = blockIdx.z;
    int n0 = blockIdx.x * 128;   // s tile
    int m0 = blockIdx.y * 128;   // t tile
    int tid = threadIdx.x;
    int tx = tid & 15, ty = tid >> 4;
    float acc[8][8] = {};

    for (int k0 = 0; k0 < HH; k0 += 16) {
        #pragma unroll
        for (int it = 0; it < 2; it++) {
            int flat = tid + it*256;
            int r = flat >> 2, c = flat & 3;
            float4 va = *(const float4*)(g_Q + ((m0 + r)*BB + b)*HH + k0 + c*4);
            As[c*4+0][r] = va.x; As[c*4+1][r] = va.y;
            As[c*4+2][r] = va.z; As[c*4+3][r] = va.w;
            float4 vb = *(const float4*)(g_K + ((n0 + r)*BB + b)*HH + k0 + c*4);
            Bs[c*4+0][r] = vb.x; Bs[c*4+1][r] = vb.y;
            Bs[c*4+2][r] = vb.z; Bs[c*4+3][r] = vb.w;
        }
        __syncthreads();
        #pragma unroll
        for (int k = 0; k < 16; k++) {
            float a[8], bb2[8];
            *(float4*)(a)    = *(const float4*)&As[k][ty*8];
            *(float4*)(a+4)  = *(const float4*)&As[k][ty*8+4];
            *(float4*)(bb2)  = *(const float4*)&Bs[k][tx*8];
            *(float4*)(bb2+4)= *(const float4*)&Bs[k][tx*8+4];
            #pragma unroll
            for (int i = 0; i < 8; i++)
                #pragma unroll
                for (int j = 0; j < 8; j++)
                    acc[i][j] += a[i]*bb2[j];
        }
        __syncthreads();
    }
    const float scale = 0.04419417382415922f;  // 512^-0.5
    #pragma unroll
    for (int j = 0; j < 8; j++) {
        float s = 0.f;
        #pragma unroll
        for (int i = 0; i < 8; i++)
            s += 1.0f / (1.0f + __expf(-acc[i][j]*scale));
        red[ty][tx*8 + j] = s;
    }
    __syncthreads();
    if (tid < 128) {
        float v = 0.f;
        #pragma unroll
        for (int yy = 0; yy < 16; yy++) v += red[yy][tid];
        g_wpart[blockIdx.y*(BB*TT) + b*TT + n0 + tid] = v;  // deterministic
    }
}

__global__ void reduce_w_kernel() {
    int i = blockIdx.x*256 + threadIdx.x;   // BB*TT = 65536
    g_wsum[i] = g_wpart[i] + g_wpart[BB*TT + i]
              + g_wpart[2*BB*TT + i] + g_wpart[3*BB*TT + i];
}

// ---------------- feat[b,d] = (1/Ttot) * sum_s wsum[b,s]*V[b,s,d] ------------
__global__ void feat_v_kernel() {
    int b = blockIdx.y;
    int d = blockIdx.x*128 + threadIdx.x;
    float acc = 0.f;
    #pragma unroll 4
    for (int s = 0; s < TT; s++)
        acc += g_wsum[b*TT + s] * g_V[(s*BB + b)*HH + d];
    g_feat[b*HH + d] = acc * (1.0f/TT);
}

// ---------------- BN over batch on feat --------------------------------------
__global__ void feat_bn_kernel(const float* __restrict__ g,
                               const float* __restrict__ bb) {
    int d = threadIdx.x;  // 512
    float s = 0.f, sq = 0.f;
    for (int b = 0; b < BB; b++) {
        float v = g_feat[b*HH + d];
        s += v; sq += v*v;
    }
    float m = s * (1.0f/BB);
    float rstd = rsqrtf(sq*(1.0f/BB) - m*m + 1e-5f);
    float gg = g[d]*rstd;
    float bo = bb[d] - m*gg;
    for (int b = 0; b < BB; b++)
        g_featn[b*HH + d] = g_feat[b*HH + d]*gg + bo;
}

// ---------------- final linear H -> 96 ---------------------------------------
__global__ void final_lin_kernel(const float* __restrict__ wh,
                                 const float* __restrict__ bh,
                                 float* __restrict__ out) {
    __shared__ float fs[HH];
    int b = blockIdx.x;
    int o = threadIdx.x;  // 96
    for (int i = o; i < HH; i += 96) fs[i] = g_featn[b*HH + i];
    __syncthreads();
    float acc = bh[o];
    for (int d = 0; d < HH; d++) acc += fs[d] * wh[o*HH + d];
    out[b*HORZ + o] = acc;
}

// ---------------- launch ------------------------------------------------------
extern "C" void kernel_launch(void* const* d_in, const int* in_sizes, int n_in,
                              void* d_out, int out_size) {
    const float* x        = (const float*)d_in[0];
    const float* conv_w   = (const float*)d_in[1];
    const float* conv_b   = (const float*)d_in[2];
    const float* bn1_g    = (const float*)d_in[3];
    const float* bn1_b    = (const float*)d_in[4];
    const float* beta_enc = (const float*)d_in[5];
    const float* bn2_g    = (const float*)d_in[6];
    const float* bn2_b    = (const float*)d_in[7];
    const float* beta2    = (const float*)d_in[8];
    const float* bn3_g    = (const float*)d_in[9];
    const float* bn3_b    = (const float*)d_in[10];
    const float* beta3    = (const float*)d_in[11];
    const float* wq       = (const float*)d_in[12];
    const float* bq       = (const float*)d_in[13];
    const float* wk       = (const float*)d_in[14];
    const float* bk       = (const float*)d_in[15];
    const float* wv       = (const float*)d_in[16];
    const float* bv       = (const float*)d_in[17];
    const float* bna_g    = (const float*)d_in[18];
    const float* bna_b    = (const float*)d_in[19];
    const float* wh       = (const float*)d_in[20];
    const float* bh       = (const float*)d_in[21];
    float* out = (float*)d_out;

    conv_kernel<<<dim3(NCHN/8, BB), 128>>>(x, conv_w, conv_b);
    chan_stats_kernel<<<NCHN, 256>>>();
    bn1_apply_kernel<<<NELEM/256, 256>>>(bn1_g, bn1_b);

    lif_scan_kernel<<<512, 128>>>(beta_enc, 0);   // A -> B (spikes)
    bn_step_kernel<<<dim3(TT, 4), 128>>>(bn2_g, bn2_b);  // B -> A
    lif_scan_kernel<<<512, 128>>>(beta2, 0);      // A -> B
    bn_step_kernel<<<dim3(TT, 4), 128>>>(bn3_g, bn3_b);  // B -> A
    lif_scan_kernel<<<512, 128>>>(beta3, 1);      // A -> B (mem3)

    gemm_xwT_kernel<<<dim3(HH/128, (TT*BB)/128), 256>>>(0, wq, bq);
    gemm_xwT_kernel<<<dim3(HH/128, (TT*BB)/128), 256>>>(1, wk, bk);
    gemm_xwT_kernel<<<dim3(HH/128, (TT*BB)/128), 256>>>(2, wv, bv);

    qk_attn_kernel<<<dim3(TT/128, TT/128, BB), 256>>>();
    reduce_w_kernel<<<(BB*TT)/256, 256>>>();
    feat_v_kernel<<<dim3(HH/128, BB), 128>>>();
    feat_bn_kernel<<<1, HH>>>(bna_g, bna_b);
    final_lin_kernel<<<BB, HORZ>>>(wh, bh, out);
}

// round 4
// speedup vs baseline: 1.2448x; 1.2448x over previous
#include <cuda_runtime.h>
#include <cuda_bf16.h>
#include <mma.h>
#include <stdint.h>
#include <math.h>

using namespace nvcuda;

#define TT   512
#define BB   128
#define HH   512
#define CC   32
#define TIN  128
#define NCHN 2048
#define HORZ 96
#define NELEM (TT*BB*HH)

// ---------------- scratch ----------------
__device__ float g_conv[BB*NCHN*TIN];
__device__ float g_bufA[NELEM];
__device__ float g_bufB[NELEM];
__device__ float g_Q[NELEM];
__device__ float g_K[NELEM];
__device__ float g_V[NELEM];
__device__ float g_wpart[4*BB*TT];
__device__ float g_wsum[BB*TT];
__device__ float g_feat[BB*HH];
__device__ float g_featn[BB*HH];
__device__ float g_chm[NCHN];
__device__ float g_chr[NCHN];

__device__ __forceinline__ void split2(float x, float y, uint32_t& hi, uint32_t& lo) {
    __nv_bfloat16 hx = __float2bfloat16(x), hy = __float2bfloat16(y);
    __nv_bfloat16 lx = __float2bfloat16(x - __bfloat162float(hx));
    __nv_bfloat16 ly = __float2bfloat16(y - __bfloat162float(hy));
    __nv_bfloat162 h(hx, hy), l(lx, ly);
    hi = *(uint32_t*)&h; lo = *(uint32_t*)&l;
}

// ============== conv / bn1 / lif / bn_step (spike path, R1-identical) =========
__global__ void conv_kernel(const float* __restrict__ x,
                            const float* __restrict__ w,
                            const float* __restrict__ cb) {
    __shared__ float xs[130][33];
    __shared__ float ws[8*96];
    int b  = blockIdx.y;
    int c0 = blockIdx.x * 8;
    int t  = threadIdx.x;
    for (int i = t; i < 130*32; i += 128) {
        int r = i >> 5, ci = i & 31;
        int tt = r - 1;
        xs[r][ci] = (tt >= 0 && tt < TIN) ? x[(b*TIN + tt)*CC + ci] : 0.0f;
    }
    for (int i = t; i < 8*96; i += 128) ws[i] = w[c0*96 + i];
    __syncthreads();
    float acc[8];
    #pragma unroll
    for (int cc = 0; cc < 8; cc++) acc[cc] = cb[c0+cc];
    #pragma unroll
    for (int i = 0; i < 32; i++) {
        float x0 = xs[t][i], x1 = xs[t+1][i], x2 = xs[t+2][i];
        #pragma unroll
        for (int cc = 0; cc < 8; cc++) {
            acc[cc] += ws[cc*96 + i*3+0]*x0 + ws[cc*96 + i*3+1]*x1 + ws[cc*96 + i*3+2]*x2;
        }
    }
    #pragma unroll
    for (int cc = 0; cc < 8; cc++)
        g_conv[(b*NCHN + c0+cc)*TIN + t] = acc[cc];
}

__global__ void chan_stats_kernel() {
    int c = blockIdx.x;
    int tid = threadIdx.x;
    float s = 0.f, sq = 0.f;
    for (int i = tid; i < BB*TIN; i += 256) {
        int b = i >> 7, t = i & 127;
        float v = g_conv[(b*NCHN + c)*TIN + t];
        s += v; sq += v*v;
    }
    __shared__ float ss[256], sqs[256];
    ss[tid] = s; sqs[tid] = sq;
    __syncthreads();
    for (int o = 128; o > 0; o >>= 1) {
        if (tid < o) { ss[tid] += ss[tid+o]; sqs[tid] += sqs[tid+o]; }
        __syncthreads();
    }
    if (tid == 0) {
        float m   = ss[0] * (1.0f/(BB*TIN));
        float var = sqs[0] * (1.0f/(BB*TIN)) - m*m;
        g_chm[c] = m;
        g_chr[c] = rsqrtf(var + 1e-5f);
    }
}

__global__ void bn1_apply_kernel(const float* __restrict__ g,
                                 const float* __restrict__ bb) {
    int idx = blockIdx.x*256 + threadIdx.x;
    int hh  = idx & 511;
    int b   = (idx >> 9) & 127;
    int tau = idx >> 16;
    int t   = tau >> 2, ts = tau & 3;
    int c   = ts*HH + hh;
    float v = g_conv[(b*NCHN + c)*TIN + t];
    g_bufA[idx] = (v - g_chm[c]) * g_chr[c] * g[c] + bb[c];
}

__global__ void lif_scan_kernel(const float* __restrict__ beta_arr, int store_mem) {
    int idx = blockIdx.x*blockDim.x + threadIdx.x;
    float beta = fminf(fmaxf(beta_arr[idx & 511], 0.0f), 0.99f);
    float mem = 0.0f;
    #pragma unroll 8
    for (int t = 0; t < TT; t++) {
        float cur   = g_bufA[t*(BB*HH) + idx];
        float reset = (mem > 1.0f) ? 1.0f : 0.0f;
        mem = beta*mem + cur - reset;
        float sp = (mem > 1.0f) ? 1.0f : 0.0f;
        g_bufB[t*(BB*HH) + idx] = store_mem ? mem : sp;
    }
}

__global__ void bn_step_kernel(const float* __restrict__ g,
                               const float* __restrict__ bb) {
    int t = blockIdx.x;
    int h = blockIdx.y*128 + threadIdx.x;
    int base = t*(BB*HH) + h;
    float s = 0.f, sq = 0.f;
    #pragma unroll 4
    for (int b = 0; b < BB; b++) {
        float v = g_bufB[base + b*HH];
        s += v; sq += v*v;
    }
    float m    = s * (1.0f/BB);
    float rstd = rsqrtf(sq*(1.0f/BB) - m*m + 1e-5f);
    float gg = g[h]*rstd;
    float bo = bb[h] - m*gg;
    #pragma unroll 4
    for (int b = 0; b < BB; b++)
        g_bufA[base + b*HH] = g_bufB[base + b*HH]*gg + bo;
}

// ============== wmma GEMM common pieces ==============
#define BK   32
#define LDA  40         // bf16 elements per smem row (80B, 16B-multiple)
#define LDS  132        // f32 stage stride (528B, 16B-multiple)
#define SM_TILES   (4*128*LDA*2)     // 40960 B: Ahi, Alo, Bhi, Blo
#define SM_DYN     (128*LDS*4)       // 67584 B stage (superset of tiles)

// Loads one 128xBK fp32 tile from src rows with given row stride, splits to
// hi/lo bf16 smem tiles. 256 threads: r = tid>>1 (row), half = tid&1.
__device__ __forceinline__ void load_split_tile(
        const float* __restrict__ src, size_t row_stride, int k0,
        __nv_bfloat16* sHi, __nv_bfloat16* sLo, int r, int half) {
    const float* p = src + (size_t)r*row_stride + k0 + half*16;
    uint32_t* dh = (uint32_t*)(sHi + r*LDA + half*16);
    uint32_t* dl = (uint32_t*)(sLo + r*LDA + half*16);
    #pragma unroll
    for (int i = 0; i < 4; i++) {
        float4 v = *(const float4*)(p + i*4);
        uint32_t h0, l0, h1, l1;
        split2(v.x, v.y, h0, l0); split2(v.z, v.w, h1, l1);
        dh[i*2] = h0; dh[i*2+1] = h1;
        dl[i*2] = l0; dl[i*2+1] = l1;
    }
}

typedef wmma::fragment<wmma::matrix_a, 16,16,16, __nv_bfloat16, wmma::row_major> FragA;
typedef wmma::fragment<wmma::matrix_b, 16,16,16, __nv_bfloat16, wmma::col_major> FragB;
typedef wmma::fragment<wmma::accumulator, 16,16,16, float> FragC;

// Core 128x128 mainloop: A rows via strideA from baseA, B rows via strideB.
// Result left in stage (row-major, LDS stride).
__device__ __forceinline__ void mma_tile_128(
        const float* baseA, size_t strideA,
        const float* baseB, size_t strideB,
        char* sm, float* stage) {
    __nv_bfloat16* sAhi = (__nv_bfloat16*)sm;
    __nv_bfloat16* sAlo = sAhi + 128*LDA;
    __nv_bfloat16* sBhi = sAlo + 128*LDA;
    __nv_bfloat16* sBlo = sBhi + 128*LDA;

    int tid = threadIdx.x, wid = tid >> 5;
    int r = tid >> 1, half = tid & 1;
    int wm = (wid & 1) * 64;      // warp m offset
    int wn = (wid >> 1) * 32;     // warp n offset

    FragC acc[4][2];
    #pragma unroll
    for (int i = 0; i < 4; i++)
        #pragma unroll
        for (int j = 0; j < 2; j++)
            wmma::fill_fragment(acc[i][j], 0.0f);

    for (int k0 = 0; k0 < HH; k0 += BK) {
        load_split_tile(baseA, strideA, k0, sAhi, sAlo, r, half);
        load_split_tile(baseB, strideB, k0, sBhi, sBlo, r, half);
        __syncthreads();
        #pragma unroll
        for (int kk = 0; kk < BK; kk += 16) {
            FragA ah[4], al[4];
            #pragma unroll
            for (int i = 0; i < 4; i++) {
                wmma::load_matrix_sync(ah[i], sAhi + (wm + i*16)*LDA + kk, LDA);
                wmma::load_matrix_sync(al[i], sAlo + (wm + i*16)*LDA + kk, LDA);
            }
            #pragma unroll
            for (int j = 0; j < 2; j++) {
                FragB bh, bl;
                wmma::load_matrix_sync(bh, sBhi + (wn + j*16)*LDA + kk, LDA);
                wmma::load_matrix_sync(bl, sBlo + (wn + j*16)*LDA + kk, LDA);
                #pragma unroll
                for (int i = 0; i < 4; i++) {
                    wmma::mma_sync(acc[i][j], ah[i], bh, acc[i][j]);
                    wmma::mma_sync(acc[i][j], ah[i], bl, acc[i][j]);
                    wmma::mma_sync(acc[i][j], al[i], bh, acc[i][j]);
                }
            }
        }
        __syncthreads();
    }
    #pragma unroll
    for (int i = 0; i < 4; i++)
        #pragma unroll
        for (int j = 0; j < 2; j++)
            wmma::store_matrix_sync(stage + (wm + i*16)*LDS + wn + j*16,
                                    acc[i][j], LDS, wmma::mem_row_major);
    __syncthreads();
}

// ============== QKV: C(sel) = mem3 @ W^T + bias ==============
__global__ __launch_bounds__(256, 1) void qkv_mma_kernel(
        const float* __restrict__ Wq, const float* __restrict__ bq,
        const float* __restrict__ Wk, const float* __restrict__ bk,
        const float* __restrict__ Wv, const float* __restrict__ bv) {
    extern __shared__ char sm[];
    float* stage = (float*)sm;
    int sel = blockIdx.z;
    const float* W    = (sel == 0) ? Wq : (sel == 1) ? Wk : Wv;
    const float* bias = (sel == 0) ? bq : (sel == 1) ? bk : bv;
    float* C          = (sel == 0) ? g_Q : (sel == 1) ? g_K : g_V;
    int n0 = blockIdx.x * 128, m0 = blockIdx.y * 128;

    mma_tile_128(g_bufB + (size_t)m0*HH, HH, W + (size_t)n0*HH, HH, sm, stage);

    int tid = threadIdx.x;
    int c = tid & 127, rr = tid >> 7;
    float bs = bias[n0 + c];
    for (int r2 = rr; r2 < 128; r2 += 2)
        C[(size_t)(m0 + r2)*HH + n0 + c] = stage[r2*LDS + c] + bs;
}

// ============== attention: sigmoid(QK^T * s) column sums ==============
__global__ __launch_bounds__(256, 1) void attn_mma_kernel() {
    extern __shared__ char sm[];
    float* stage = (float*)sm;
    int b  = blockIdx.z;
    int n0 = blockIdx.x * 128;   // s tile
    int m0 = blockIdx.y * 128;   // t tile

    mma_tile_128(g_Q + ((size_t)m0*BB + b)*HH, (size_t)BB*HH,
                 g_K + ((size_t)n0*BB + b)*HH, (size_t)BB*HH, sm, stage);

    const float scale = 0.04419417382415922f;  // 512^-0.5
    int tid = threadIdx.x;
    if (tid < 128) {
        float s = 0.f;
        #pragma unroll 4
        for (int rr = 0; rr < 128; rr++) {
            float v = stage[rr*LDS + tid];
            s += 1.0f / (1.0f + __expf(-v*scale));
        }
        g_wpart[blockIdx.y*(BB*TT) + b*TT + n0 + tid] = s;
    }
}

// ============== tail kernels (R1-identical) ==============
__global__ void reduce_w_kernel() {
    int i = blockIdx.x*256 + threadIdx.x;
    g_wsum[i] = g_wpart[i] + g_wpart[BB*TT + i]
              + g_wpart[2*BB*TT + i] + g_wpart[3*BB*TT + i];
}

__global__ void feat_v_kernel() {
    int b = blockIdx.y;
    int d = blockIdx.x*128 + threadIdx.x;
    float acc = 0.f;
    #pragma unroll 4
    for (int s = 0; s < TT; s++)
        acc += g_wsum[b*TT + s] * g_V[(s*BB + b)*HH + d];
    g_feat[b*HH + d] = acc * (1.0f/TT);
}

__global__ void feat_bn_kernel(const float* __restrict__ g,
                               const float* __restrict__ bb) {
    int d = threadIdx.x;
    float s = 0.f, sq = 0.f;
    for (int b = 0; b < BB; b++) {
        float v = g_feat[b*HH + d];
        s += v; sq += v*v;
    }
    float m = s * (1.0f/BB);
    float rstd = rsqrtf(sq*(1.0f/BB) - m*m + 1e-5f);
    float gg = g[d]*rstd;
    float bo = bb[d] - m*gg;
    for (int b = 0; b < BB; b++)
        g_featn[b*HH + d] = g_feat[b*HH + d]*gg + bo;
}

__global__ void final_lin_kernel(const float* __restrict__ wh,
                                 const float* __restrict__ bh,
                                 float* __restrict__ out) {
    __shared__ float fs[HH];
    int b = blockIdx.x;
    int o = threadIdx.x;
    for (int i = o; i < HH; i += 96) fs[i] = g_featn[b*HH + i];
    __syncthreads();
    float acc = bh[o];
    for (int d = 0; d < HH; d++) acc += fs[d] * wh[o*HH + d];
    out[b*HORZ + o] = acc;
}

// ---------------- launch ------------------------------------------------------
extern "C" void kernel_launch(void* const* d_in, const int* in_sizes, int n_in,
                              void* d_out, int out_size) {
    const float* x        = (const float*)d_in[0];
    const float* conv_w   = (const float*)d_in[1];
    const float* conv_b   = (const float*)d_in[2];
    const float* bn1_g    = (const float*)d_in[3];
    const float* bn1_b    = (const float*)d_in[4];
    const float* beta_enc = (const float*)d_in[5];
    const float* bn2_g    = (const float*)d_in[6];
    const float* bn2_b    = (const float*)d_in[7];
    const float* beta2    = (const float*)d_in[8];
    const float* bn3_g    = (const float*)d_in[9];
    const float* bn3_b    = (const float*)d_in[10];
    const float* beta3    = (const float*)d_in[11];
    const float* wq       = (const float*)d_in[12];
    const float* bq       = (const float*)d_in[13];
    const float* wk       = (const float*)d_in[14];
    const float* bk       = (const float*)d_in[15];
    const float* wv       = (const float*)d_in[16];
    const float* bv       = (const float*)d_in[17];
    const float* bna_g    = (const float*)d_in[18];
    const float* bna_b    = (const float*)d_in[19];
    const float* wh       = (const float*)d_in[20];
    const float* bh       = (const float*)d_in[21];
    float* out = (float*)d_out;

    cudaFuncSetAttribute(qkv_mma_kernel,  cudaFuncAttributeMaxDynamicSharedMemorySize, SM_DYN);
    cudaFuncSetAttribute(attn_mma_kernel, cudaFuncAttributeMaxDynamicSharedMemorySize, SM_DYN);

    conv_kernel<<<dim3(NCHN/8, BB), 128>>>(x, conv_w, conv_b);
    chan_stats_kernel<<<NCHN, 256>>>();
    bn1_apply_kernel<<<NELEM/256, 256>>>(bn1_g, bn1_b);

    lif_scan_kernel<<<512, 128>>>(beta_enc, 0);
    bn_step_kernel<<<dim3(TT, 4), 128>>>(bn2_g, bn2_b);
    lif_scan_kernel<<<512, 128>>>(beta2, 0);
    bn_step_kernel<<<dim3(TT, 4), 128>>>(bn3_g, bn3_b);
    lif_scan_kernel<<<512, 128>>>(beta3, 1);

    qkv_mma_kernel<<<dim3(HH/128, (TT*BB)/128, 3), 256, SM_DYN>>>(wq, bq, wk, bk, wv, bv);
    attn_mma_kernel<<<dim3(TT/128, TT/128, BB), 256, SM_DYN>>>();

    reduce_w_kernel<<<(BB*TT)/256, 256>>>();
    feat_v_kernel<<<dim3(HH/128, BB), 128>>>();
    feat_bn_kernel<<<1, HH>>>(bna_g, bna_b);
    final_lin_kernel<<<BB, HORZ>>>(wh, bh, out);
}

// round 5
// speedup vs baseline: 1.7475x; 1.4039x over previous
#include <cuda_runtime.h>
#include <cuda_bf16.h>
#include <mma.h>
#include <stdint.h>
#include <math.h>

using namespace nvcuda;

#define TT   512
#define BB   128
#define HH   512
#define CC   32
#define TIN  128
#define NCHN 2048
#define HORZ 96
#define NELEM (TT*BB*HH)

// ---------------- scratch ----------------
__device__ float g_conv[BB*NCHN*TIN];   // (B, 2048, Tin)
__device__ float g_bufA[NELEM];         // X after bn1: (tau, h, b)
__device__ float g_bufB[NELEM];         // mem3:        (tau, h, b)
__device__ float g_Q[NELEM];            // (m = t*BB+b, n)
__device__ float g_K[NELEM];
__device__ float g_V[NELEM];
__device__ float g_wpart[4*BB*TT];
__device__ float g_wsum[BB*TT];
__device__ float g_feat[BB*HH];
__device__ float g_featn[BB*HH];
__device__ float g_chm[NCHN];
__device__ float g_chr[NCHN];

__device__ __forceinline__ void split2(float x, float y, uint32_t& hi, uint32_t& lo) {
    __nv_bfloat16 hx = __float2bfloat16(x), hy = __float2bfloat16(y);
    __nv_bfloat16 lx = __float2bfloat16(x - __bfloat162float(hx));
    __nv_bfloat16 ly = __float2bfloat16(y - __bfloat162float(hy));
    __nv_bfloat162 h(hx, hy), l(lx, ly);
    hi = *(uint32_t*)&h; lo = *(uint32_t*)&l;
}

// ============== conv + channel stats (R1-identical) ==============
__global__ void conv_kernel(const float* __restrict__ x,
                            const float* __restrict__ w,
                            const float* __restrict__ cb) {
    __shared__ float xs[130][33];
    __shared__ float ws[8*96];
    int b  = blockIdx.y;
    int c0 = blockIdx.x * 8;
    int t  = threadIdx.x;
    for (int i = t; i < 130*32; i += 128) {
        int r = i >> 5, ci = i & 31;
        int tt = r - 1;
        xs[r][ci] = (tt >= 0 && tt < TIN) ? x[(b*TIN + tt)*CC + ci] : 0.0f;
    }
    for (int i = t; i < 8*96; i += 128) ws[i] = w[c0*96 + i];
    __syncthreads();
    float acc[8];
    #pragma unroll
    for (int cc = 0; cc < 8; cc++) acc[cc] = cb[c0+cc];
    #pragma unroll
    for (int i = 0; i < 32; i++) {
        float x0 = xs[t][i], x1 = xs[t+1][i], x2 = xs[t+2][i];
        #pragma unroll
        for (int cc = 0; cc < 8; cc++) {
            acc[cc] += ws[cc*96 + i*3+0]*x0 + ws[cc*96 + i*3+1]*x1 + ws[cc*96 + i*3+2]*x2;
        }
    }
    #pragma unroll
    for (int cc = 0; cc < 8; cc++)
        g_conv[(b*NCHN + c0+cc)*TIN + t] = acc[cc];
}

__global__ void chan_stats_kernel() {
    int c = blockIdx.x;
    int tid = threadIdx.x;
    float s = 0.f, sq = 0.f;
    for (int i = tid; i < BB*TIN; i += 256) {
        int b = i >> 7, t = i & 127;
        float v = g_conv[(b*NCHN + c)*TIN + t];
        s += v; sq += v*v;
    }
    __shared__ float ss[256], sqs[256];
    ss[tid] = s; sqs[tid] = sq;
    __syncthreads();
    for (int o = 128; o > 0; o >>= 1) {
        if (tid < o) { ss[tid] += ss[tid+o]; sqs[tid] += sqs[tid+o]; }
        __syncthreads();
    }
    if (tid == 0) {
        float m   = ss[0] * (1.0f/(BB*TIN));
        float var = sqs[0] * (1.0f/(BB*TIN)) - m*m;
        g_chm[c] = m;
        g_chr[c] = rsqrtf(var + 1e-5f);
    }
}

// ============== BN1 apply + transpose -> (tau, h, b) ==============
__global__ void bn1t_kernel(const float* __restrict__ g,
                            const float* __restrict__ bb) {
    __shared__ float sm_t[128*33];
    int c = blockIdx.x, bq = blockIdx.y;
    int ts = c >> 9, h = c & 511;
    int tid = threadIdx.x;
    float chm = g_chm[c], chr = g_chr[c], gg = g[c], bo = bb[c];
    int bl = tid >> 2, tq = tid & 3;
    int b = bq*32 + bl;
    const float* src = g_conv + ((size_t)b*NCHN + c)*TIN;
    #pragma unroll
    for (int it = 0; it < 8; it++) {
        int tbase = (tq + it*4)*4;
        float4 v = *(const float4*)(src + tbase);
        sm_t[(tbase+0)*33 + bl] = (v.x - chm) * chr * gg + bo;
        sm_t[(tbase+1)*33 + bl] = (v.y - chm) * chr * gg + bo;
        sm_t[(tbase+2)*33 + bl] = (v.z - chm) * chr * gg + bo;
        sm_t[(tbase+3)*33 + bl] = (v.w - chm) * chr * gg + bo;
    }
    __syncthreads();
    int bl2 = tid & 31, tch = tid >> 5;
    #pragma unroll 8
    for (int it = 0; it < 32; it++) {
        int t = tch*32 + it;
        g_bufA[((size_t)(t*4 + ts)*HH + h)*BB + bq*32 + bl2] = sm_t[t*33 + bl2];
    }
}

// ============== fused lif1 -> bn2 -> lif2 -> bn3 -> lif3 ==============
// block = one h, 128 threads = batch. Spikes binary => BN stats via ballot/popc
// (exact integers, bitwise-identical to serial float sum of 0/1).
__global__ __launch_bounds__(128) void snn_fused_kernel(
        const float* __restrict__ be,  const float* __restrict__ g2a,
        const float* __restrict__ b2a, const float* __restrict__ be2,
        const float* __restrict__ g3a, const float* __restrict__ b3a,
        const float* __restrict__ be3) {
    __shared__ int scnt[2][2][4];   // [stage][t-parity][warp]
    int tid = threadIdx.x;
    int h = blockIdx.x;
    int warp = tid >> 5, lane = tid & 31;
    float beta1 = fminf(fmaxf(be[h],  0.0f), 0.99f);
    float beta2 = fminf(fmaxf(be2[h], 0.0f), 0.99f);
    float beta3 = fminf(fmaxf(be3[h], 0.0f), 0.99f);
    float g2 = g2a[h], b2 = b2a[h], g3 = g3a[h], b3 = b3a[h];
    const float* src = g_bufA + (size_t)h*BB + tid;
    float* dst       = g_bufB + (size_t)h*BB + tid;
    float mem1 = 0.f, mem2 = 0.f, mem3 = 0.f;

    float cur[4];
    #pragma unroll
    for (int j = 0; j < 4; j++) cur[j] = src[(size_t)j*HH*BB];

    for (int t0 = 0; t0 < TT; t0 += 4) {
        float nxt[4] = {0.f, 0.f, 0.f, 0.f};
        if (t0 + 4 < TT) {
            #pragma unroll
            for (int j = 0; j < 4; j++) nxt[j] = src[(size_t)(t0+4+j)*HH*BB];
        }
        #pragma unroll
        for (int j = 0; j < 4; j++) {
            int t = t0 + j, par = t & 1;
            float reset = (mem1 > 1.0f) ? 1.0f : 0.0f;
            mem1 = beta1*mem1 + cur[j] - reset;
            float s1 = (mem1 > 1.0f) ? 1.0f : 0.0f;
            unsigned bal = __ballot_sync(0xffffffffu, mem1 > 1.0f);
            if (lane == 0) scnt[0][par][warp] = __popc(bal);
            __syncthreads();
            float sq = (float)(scnt[0][par][0] + scnt[0][par][1]
                             + scnt[0][par][2] + scnt[0][par][3]);
            float m    = sq * (1.0f/BB);
            float rstd = rsqrtf(sq*(1.0f/BB) - m*m + 1e-5f);
            float gg = g2*rstd;
            float bo = b2 - m*gg;
            float h2 = s1*gg + bo;

            float reset2 = (mem2 > 1.0f) ? 1.0f : 0.0f;
            mem2 = beta2*mem2 + h2 - reset2;
            float s2 = (mem2 > 1.0f) ? 1.0f : 0.0f;
            bal = __ballot_sync(0xffffffffu, mem2 > 1.0f);
            if (lane == 0) scnt[1][par][warp] = __popc(bal);
            __syncthreads();
            sq = (float)(scnt[1][par][0] + scnt[1][par][1]
                       + scnt[1][par][2] + scnt[1][par][3]);
            m    = sq * (1.0f/BB);
            rstd = rsqrtf(sq*(1.0f/BB) - m*m + 1e-5f);
            gg = g3*rstd;
            bo = b3 - m*gg;
            float h3 = s2*gg + bo;

            float reset3 = (mem3 > 1.0f) ? 1.0f : 0.0f;
            mem3 = beta3*mem3 + h3 - reset3;
            dst[(size_t)t*HH*BB] = mem3;
        }
        #pragma unroll
        for (int j = 0; j < 4; j++) cur[j] = nxt[j];
    }
}

// ============== wmma GEMM pieces ==============
#define BK   32
#define LDA  40          // bf16 row stride for k-contiguous tiles
#define LDAT 136         // bf16 row stride for b-contiguous (transposed) A tiles
#define LDS  132         // fp32 stage stride
#define SM_DYN (128*LDS*4)   // 67584 B

__device__ __forceinline__ void load_split_tile(
        const float* __restrict__ src, size_t row_stride, int k0,
        __nv_bfloat16* sHi, __nv_bfloat16* sLo, int r, int half) {
    const float* p = src + (size_t)r*row_stride + k0 + half*16;
    uint32_t* dh = (uint32_t*)(sHi + r*LDA + half*16);
    uint32_t* dl = (uint32_t*)(sLo + r*LDA + half*16);
    #pragma unroll
    for (int i = 0; i < 4; i++) {
        float4 v = *(const float4*)(p + i*4);
        uint32_t h0, l0, h1, l1;
        split2(v.x, v.y, h0, l0); split2(v.z, v.w, h1, l1);
        dh[i*2] = h0; dh[i*2+1] = h1;
        dl[i*2] = l0; dl[i*2+1] = l1;
    }
}

typedef wmma::fragment<wmma::matrix_a, 16,16,16, __nv_bfloat16, wmma::row_major> FragA;
typedef wmma::fragment<wmma::matrix_a, 16,16,16, __nv_bfloat16, wmma::col_major> FragAc;
typedef wmma::fragment<wmma::matrix_b, 16,16,16, __nv_bfloat16, wmma::col_major> FragB;
typedef wmma::fragment<wmma::accumulator, 16,16,16, float> FragC;

// ============== QKV: C(sel) = mem3 @ W^T + bias ==============
// mem3 layout (t, k, b): the A tile (b rows x k cols) is natively col-major.
// grid (12, 512): x = sel*4 + ntile so all 12 blocks sharing one A-tile are
// launch-adjacent (A read once from DRAM, rest from L2).
__global__ __launch_bounds__(256) void qkv_mma_kernel(
        const float* __restrict__ Wq, const float* __restrict__ bq,
        const float* __restrict__ Wk, const float* __restrict__ bk,
        const float* __restrict__ Wv, const float* __restrict__ bv) {
    extern __shared__ char sm[];
    __nv_bfloat16* sAhi = (__nv_bfloat16*)sm;          // 32 x LDAT
    __nv_bfloat16* sAlo = sAhi + 32*LDAT;
    __nv_bfloat16* sBhi = sAlo + 32*LDAT;              // 128 x LDA
    __nv_bfloat16* sBlo = sBhi + 128*LDA;
    float* stage = (float*)sm;

    int bx = blockIdx.x;
    int ntile = bx & 3, sel = bx >> 2;
    int t = blockIdx.y;
    int n0 = ntile*128, m0 = t*128;
    const float* W    = (sel == 0) ? Wq : (sel == 1) ? Wk : Wv;
    const float* bias = (sel == 0) ? bq : (sel == 1) ? bk : bv;
    float* C          = (sel == 0) ? g_Q : (sel == 1) ? g_K : g_V;

    int tid = threadIdx.x, wid = tid >> 5;
    int wm = (wid & 1) * 64, wn = (wid >> 1) * 32;

    FragC acc[4][2];
    #pragma unroll
    for (int i = 0; i < 4; i++)
        #pragma unroll
        for (int j = 0; j < 2; j++)
            wmma::fill_fragment(acc[i][j], 0.0f);

    for (int k0 = 0; k0 < HH; k0 += BK) {
        // A tile: g_bufB[(t*HH + k0+k)*BB + b], b-contiguous loads
        {
            int k = tid >> 3;
            int bo_ = (tid & 7) * 4;
            const float* ap = g_bufB + ((size_t)t*HH + k0 + k)*BB;
            #pragma unroll
            for (int it = 0; it < 4; it++) {
                int bpos = bo_ + it*32;
                float4 v = *(const float4*)(ap + bpos);
                uint32_t h0, l0, h1, l1;
                split2(v.x, v.y, h0, l0); split2(v.z, v.w, h1, l1);
                *(uint32_t*)(sAhi + k*LDAT + bpos)     = h0;
                *(uint32_t*)(sAhi + k*LDAT + bpos + 2) = h1;
                *(uint32_t*)(sAlo + k*LDAT + bpos)     = l0;
                *(uint32_t*)(sAlo + k*LDAT + bpos + 2) = l1;
            }
        }
        load_split_tile(W + (size_t)n0*HH, HH, k0, sBhi, sBlo, tid >> 1, tid & 1);
        __syncthreads();
        #pragma unroll
        for (int kk = 0; kk < BK; kk += 16) {
            FragAc ah[4], al[4];
            #pragma unroll
            for (int i = 0; i < 4; i++) {
                wmma::load_matrix_sync(ah[i], sAhi + kk*LDAT + wm + i*16, LDAT);
                wmma::load_matrix_sync(al[i], sAlo + kk*LDAT + wm + i*16, LDAT);
            }
            #pragma unroll
            for (int j = 0; j < 2; j++) {
                FragB bh, bl;
                wmma::load_matrix_sync(bh, sBhi + (wn + j*16)*LDA + kk, LDA);
                wmma::load_matrix_sync(bl, sBlo + (wn + j*16)*LDA + kk, LDA);
                #pragma unroll
                for (int i = 0; i < 4; i++) {
                    wmma::mma_sync(acc[i][j], ah[i], bh, acc[i][j]);
                    wmma::mma_sync(acc[i][j], ah[i], bl, acc[i][j]);
                    wmma::mma_sync(acc[i][j], al[i], bh, acc[i][j]);
                }
            }
        }
        __syncthreads();
    }
    #pragma unroll
    for (int i = 0; i < 4; i++)
        #pragma unroll
        for (int j = 0; j < 2; j++)
            wmma::store_matrix_sync(stage + (wm + i*16)*LDS + wn + j*16,
                                    acc[i][j], LDS, wmma::mem_row_major);
    __syncthreads();

    int c = tid & 127, rr = tid >> 7;
    float bs = bias[n0 + c];
    for (int r2 = rr; r2 < 128; r2 += 2)
        C[(size_t)(m0 + r2)*HH + n0 + c] = stage[r2*LDS + c] + bs;
}

// ============== attention: sigmoid(QK^T * s) column sums ==============
__device__ __forceinline__ void mma_tile_128(
        const float* baseA, size_t strideA,
        const float* baseB, size_t strideB,
        char* sm, float* stage) {
    __nv_bfloat16* sAhi = (__nv_bfloat16*)sm;
    __nv_bfloat16* sAlo = sAhi + 128*LDA;
    __nv_bfloat16* sBhi = sAlo + 128*LDA;
    __nv_bfloat16* sBlo = sBhi + 128*LDA;

    int tid = threadIdx.x, wid = tid >> 5;
    int r = tid >> 1, half = tid & 1;
    int wm = (wid & 1) * 64;
    int wn = (wid >> 1) * 32;

    FragC acc[4][2];
    #pragma unroll
    for (int i = 0; i < 4; i++)
        #pragma unroll
        for (int j = 0; j < 2; j++)
            wmma::fill_fragment(acc[i][j], 0.0f);

    for (int k0 = 0; k0 < HH; k0 += BK) {
        load_split_tile(baseA, strideA, k0, sAhi, sAlo, r, half);
        load_split_tile(baseB, strideB, k0, sBhi, sBlo, r, half);
        __syncthreads();
        #pragma unroll
        for (int kk = 0; kk < BK; kk += 16) {
            FragA ah[4], al[4];
            #pragma unroll
            for (int i = 0; i < 4; i++) {
                wmma::load_matrix_sync(ah[i], sAhi + (wm + i*16)*LDA + kk, LDA);
                wmma::load_matrix_sync(al[i], sAlo + (wm + i*16)*LDA + kk, LDA);
            }
            #pragma unroll
            for (int j = 0; j < 2; j++) {
                FragB bh, bl;
                wmma::load_matrix_sync(bh, sBhi + (wn + j*16)*LDA + kk, LDA);
                wmma::load_matrix_sync(bl, sBlo + (wn + j*16)*LDA + kk, LDA);
                #pragma unroll
                for (int i = 0; i < 4; i++) {
                    wmma::mma_sync(acc[i][j], ah[i], bh, acc[i][j]);
                    wmma::mma_sync(acc[i][j], ah[i], bl, acc[i][j]);
                    wmma::mma_sync(acc[i][j], al[i], bh, acc[i][j]);
                }
            }
        }
        __syncthreads();
    }
    #pragma unroll
    for (int i = 0; i < 4; i++)
        #pragma unroll
        for (int j = 0; j < 2; j++)
            wmma::store_matrix_sync(stage + (wm + i*16)*LDS + wn + j*16,
                                    acc[i][j], LDS, wmma::mem_row_major);
    __syncthreads();
}

__global__ __launch_bounds__(256) void attn_mma_kernel() {
    extern __shared__ char sm[];
    float* stage = (float*)sm;
    int b  = blockIdx.z;
    int n0 = blockIdx.x * 128;
    int m0 = blockIdx.y * 128;

    mma_tile_128(g_Q + ((size_t)m0*BB + b)*HH, (size_t)BB*HH,
                 g_K + ((size_t)n0*BB + b)*HH, (size_t)BB*HH, sm, stage);

    const float scale = 0.04419417382415922f;  // 512^-0.5
    int tid = threadIdx.x;
    if (tid < 128) {
        float s = 0.f;
        #pragma unroll 4
        for (int rr = 0; rr < 128; rr++) {
            float v = stage[rr*LDS + tid];
            s += 1.0f / (1.0f + __expf(-v*scale));
        }
        g_wpart[blockIdx.y*(BB*TT) + b*TT + n0 + tid] = s;
    }
}

// ============== tail kernels (unchanged) ==============
__global__ void reduce_w_kernel() {
    int i = blockIdx.x*256 + threadIdx.x;
    g_wsum[i] = g_wpart[i] + g_wpart[BB*TT + i]
              + g_wpart[2*BB*TT + i] + g_wpart[3*BB*TT + i];
}

__global__ void feat_v_kernel() {
    int b = blockIdx.y;
    int d = blockIdx.x*128 + threadIdx.x;
    float acc = 0.f;
    #pragma unroll 4
    for (int s = 0; s < TT; s++)
        acc += g_wsum[b*TT + s] * g_V[(s*BB + b)*HH + d];
    g_feat[b*HH + d] = acc * (1.0f/TT);
}

__global__ void feat_bn_kernel(const float* __restrict__ g,
                               const float* __restrict__ bb) {
    int d = threadIdx.x;
    float s = 0.f, sq = 0.f;
    for (int b = 0; b < BB; b++) {
        float v = g_feat[b*HH + d];
        s += v; sq += v*v;
    }
    float m = s * (1.0f/BB);
    float rstd = rsqrtf(sq*(1.0f/BB) - m*m + 1e-5f);
    float gg = g[d]*rstd;
    float bo = bb[d] - m*gg;
    for (int b = 0; b < BB; b++)
        g_featn[b*HH + d] = g_feat[b*HH + d]*gg + bo;
}

__global__ void final_lin_kernel(const float* __restrict__ wh,
                                 const float* __restrict__ bh,
                                 float* __restrict__ out) {
    __shared__ float fs[HH];
    int b = blockIdx.x;
    int o = threadIdx.x;
    for (int i = o; i < HH; i += 96) fs[i] = g_featn[b*HH + i];
    __syncthreads();
    float acc = bh[o];
    for (int d = 0; d < HH; d++) acc += fs[d] * wh[o*HH + d];
    out[b*HORZ + o] = acc;
}

// ---------------- launch ------------------------------------------------------
extern "C" void kernel_launch(void* const* d_in, const int* in_sizes, int n_in,
                              void* d_out, int out_size) {
    const float* x        = (const float*)d_in[0];
    const float* conv_w   = (const float*)d_in[1];
    const float* conv_b   = (const float*)d_in[2];
    const float* bn1_g    = (const float*)d_in[3];
    const float* bn1_b    = (const float*)d_in[4];
    const float* beta_enc = (const float*)d_in[5];
    const float* bn2_g    = (const float*)d_in[6];
    const float* bn2_b    = (const float*)d_in[7];
    const float* beta2    = (const float*)d_in[8];
    const float* bn3_g    = (const float*)d_in[9];
    const float* bn3_b    = (const float*)d_in[10];
    const float* beta3    = (const float*)d_in[11];
    const float* wq       = (const float*)d_in[12];
    const float* bq       = (const float*)d_in[13];
    const float* wk       = (const float*)d_in[14];
    const float* bk       = (const float*)d_in[15];
    const float* wv       = (const float*)d_in[16];
    const float* bv       = (const float*)d_in[17];
    const float* bna_g    = (const float*)d_in[18];
    const float* bna_b    = (const float*)d_in[19];
    const float* wh       = (const float*)d_in[20];
    const float* bh       = (const float*)d_in[21];
    float* out = (float*)d_out;

    cudaFuncSetAttribute(qkv_mma_kernel,  cudaFuncAttributeMaxDynamicSharedMemorySize, SM_DYN);
    cudaFuncSetAttribute(attn_mma_kernel, cudaFuncAttributeMaxDynamicSharedMemorySize, SM_DYN);

    conv_kernel<<<dim3(NCHN/8, BB), 128>>>(x, conv_w, conv_b);
    chan_stats_kernel<<<NCHN, 256>>>();
    bn1t_kernel<<<dim3(NCHN, 4), 128>>>(bn1_g, bn1_b);

    snn_fused_kernel<<<HH, 128>>>(beta_enc, bn2_g, bn2_b, beta2, bn3_g, bn3_b, beta3);

    qkv_mma_kernel<<<dim3(12, TT), 256, SM_DYN>>>(wq, bq, wk, bk, wv, bv);
    attn_mma_kernel<<<dim3(TT/128, TT/128, BB), 256, SM_DYN>>>();

    reduce_w_kernel<<<(BB*TT)/256, 256>>>();
    feat_v_kernel<<<dim3(HH/128, BB), 128>>>();
    feat_bn_kernel<<<1, HH>>>(bna_g, bna_b);
    final_lin_kernel<<<BB, HORZ>>>(wh, bh, out);
}